// round 16
// baseline (speedup 1.0000x reference)
#include <cuda_runtime.h>
#include <cuda_fp16.h>
#include <math.h>

#define NN 100000
#define NE 1600000
#define NB 64
#define FD 128
#define NC 16
#define NPB 196  // ceil(NN/512) scan blocks
#define LDSH 136 // padded smem leading dim (halves) for conflict-free ldmatrix
#define NT_TOTAL ((NN + 63) / 64)   // 1563 tiles / pooling chunks
#define NT_H0 781                    // first-half tiles
#define NSPLIT (NT_H0 * 64)          // 49984: node split, 64-aligned

// ---------------- scratch (device globals; no allocations) ----------------
__device__ __half   g_h16a[NN * FD];  // fp16 h~ layer 1 = dinv * (X@W1)
__device__ __half   g_h16b[NN * FD];  // fp16 h~ layer 2 = dinv * (Z@W2)   (separate: no aliasing)
__device__ __half   g_z16[NN * FD];   // fp16 Z = relu(LN(agg))
__device__ __half   g_x16[NN * FD];   // fp16 copy of input X
__device__ __half   g_W16a[FD * FD];  // W1 in fp16
__device__ __half   g_W16b[FD * FD];  // W2 in fp16
__device__ float    g_dinv[NN];
__device__ int      g_indeg[NN];
__device__ int      g_ctr[NN];
__device__ int      g_rowptr[NN + 1];
__device__ int      g_part[NPB];
__device__ int      g_esrc[NE];
__device__ float    g_denom[NB];
__device__ float    g_pooled[NB * FD];   // unnormalized: sum of exp(gate)*z

// ---------------- helpers ----------------
__device__ __forceinline__ unsigned long long pk2(float lo, float hi) {
    unsigned long long r;
    asm("mov.b64 %0, {%1,%2};" : "=l"(r) : "f"(lo), "f"(hi));
    return r;
}
__device__ __forceinline__ void upk2(unsigned long long v, float& lo, float& hi) {
    asm("mov.b64 {%0,%1}, %2;" : "=f"(lo), "=f"(hi) : "l"(v));
}
__device__ __forceinline__ void fma2(unsigned long long& acc, unsigned long long a,
                                     unsigned long long b) {
    asm("fma.rn.f32x2 %0, %1, %2, %0;" : "+l"(acc) : "l"(a), "l"(b));
}

// ---------------- setup kernels ----------------
__global__ __launch_bounds__(256) void init_kernel() {
    int i = blockIdx.x * blockDim.x + threadIdx.x;
    if (i < NN) { g_indeg[i] = 0; g_ctr[i] = 0; }
    if (i < NB * FD) g_pooled[i] = 0.f;
    if (i < NB) g_denom[i] = 0.f;
    if (i == 0) g_rowptr[NN] = NE;
}

__global__ __launch_bounds__(256) void w16_kernel(const float* __restrict__ W,
                                                  __half* __restrict__ O) {
    int i = blockIdx.x * 256 + threadIdx.x;
    if (i < FD * FD / 2) {
        float2 v = ((const float2*)W)[i];
        ((__half2*)O)[i] = __floats2half2_rn(v.x, v.y);
    }
}

__global__ __launch_bounds__(256) void x16_kernel(const float* __restrict__ X,
                                                  __half* __restrict__ O) {
    int i = blockIdx.x * 256 + threadIdx.x;
    const int total = NN * FD / 4;  // float4 granules
    if (i < total) {
        float4 v = ((const float4*)X)[i];
        __half2 p0 = __floats2half2_rn(v.x, v.y);
        __half2 p1 = __floats2half2_rn(v.z, v.w);
        uint2 st;
        st.x = *(unsigned*)&p0;
        st.y = *(unsigned*)&p1;
        ((uint2*)O)[i] = st;
    }
}

__global__ __launch_bounds__(256) void deg_kernel(const int* __restrict__ dst) {
    int idx = blockIdx.x * blockDim.x + threadIdx.x;
    if (idx < NE / 4) {
        int4 d = ((const int4*)dst)[idx];
        atomicAdd(&g_indeg[d.x], 1);
        atomicAdd(&g_indeg[d.y], 1);
        atomicAdd(&g_indeg[d.z], 1);
        atomicAdd(&g_indeg[d.w], 1);
    }
}

__global__ __launch_bounds__(512) void scanA_kernel() {
    int t = threadIdx.x, b = blockIdx.x;
    int idx = b * 512 + t;
    int v = (idx < NN) ? g_indeg[idx] : 0;
    if (idx < NN) g_dinv[idx] = rsqrtf((float)(v + 1));
    int x = v;
#pragma unroll
    for (int o = 16; o; o >>= 1) x += __shfl_xor_sync(0xffffffffu, x, o);
    __shared__ int wsum[16];
    int lane = t & 31, wid = t >> 5;
    if (lane == 0) wsum[wid] = x;
    __syncthreads();
    if (t == 0) {
        int s = 0;
#pragma unroll
        for (int w = 0; w < 16; w++) s += wsum[w];
        g_part[b] = s;
    }
}

// fused: per-block scan of indeg + redundant scan of g_part
__global__ __launch_bounds__(512) void scanC_kernel() {
    int t = threadIdx.x, b = blockIdx.x;
    int lane = t & 31, wid = t >> 5;

    __shared__ int sp[256];
    __shared__ int blockoff;
    {
        int v = (t < NPB) ? g_part[t] : 0;
        if (t < 256) {
            int x = v;
#pragma unroll
            for (int o = 1; o < 32; o <<= 1) {
                int y = __shfl_up_sync(0xffffffffu, x, o);
                if (lane >= o) x += y;
            }
            sp[t] = x;
        }
        __syncthreads();
        if (t < 256 && wid > 0) {
            int add = 0;
#pragma unroll
            for (int w = 0; w < 8; w++)
                if (w < wid) add += sp[w * 32 + 31];
            sp[t] += add;
        }
        __syncthreads();
        if (t == 0) blockoff = (b > 0) ? sp[b - 1] : 0;
        __syncthreads();
    }

    int idx = b * 512 + t;
    int v = (idx < NN) ? g_indeg[idx] : 0;
    int x = v;
#pragma unroll
    for (int o = 1; o < 32; o <<= 1) {
        int y = __shfl_up_sync(0xffffffffu, x, o);
        if (lane >= o) x += y;
    }
    __shared__ int wsum[16];
    if (lane == 31) wsum[wid] = x;
    __syncthreads();
    if (wid == 0) {
        int s = (lane < 16) ? wsum[lane] : 0;
#pragma unroll
        for (int o = 1; o < 16; o <<= 1) {
            int y = __shfl_up_sync(0xffffffffu, s, o);
            if (lane >= o) s += y;
        }
        if (lane < 16) wsum[lane] = s;
    }
    __syncthreads();
    int excl = x - v + (wid > 0 ? wsum[wid - 1] : 0);
    if (idx < NN) g_rowptr[idx] = blockoff + excl;
}

__global__ __launch_bounds__(256) void fill_kernel(const int* __restrict__ src,
                                                   const int* __restrict__ dst) {
    int e = blockIdx.x * blockDim.x + threadIdx.x;
    if (e < NE) {
        int d = dst[e];
        int p = g_rowptr[d] + atomicAdd(&g_ctr[d], 1);
        g_esrc[p] = src[e];
    }
}

// ---------------- shared GEMM core ----------------
__device__ __forceinline__ void gemm_tile_compute(const __half* sA, const __half* sW,
                                                  int mrow, int ncol0, int lane,
                                                  float acc[8][4]) {
#pragma unroll
    for (int nt = 0; nt < 8; nt++)
        acc[nt][0] = acc[nt][1] = acc[nt][2] = acc[nt][3] = 0.f;
#pragma unroll
    for (int k0 = 0; k0 < 128; k0 += 16) {
        unsigned a0, a1, a2, a3;
        {
            int arow = mrow + (lane & 15);
            int acol = k0 + ((lane >> 4) << 3);
            unsigned aaddr = (unsigned)__cvta_generic_to_shared(&sA[arow * LDSH + acol]);
            asm volatile("ldmatrix.sync.aligned.m8n8.x4.shared.b16 {%0,%1,%2,%3}, [%4];"
                         : "=r"(a0), "=r"(a1), "=r"(a2), "=r"(a3) : "r"(aaddr));
        }
#pragma unroll
        for (int np = 0; np < 4; np++) {
            unsigned b0, b1, b2, b3;
            unsigned baddr = (unsigned)__cvta_generic_to_shared(
                &sW[(k0 + (lane & 15)) * LDSH + ncol0 + np * 16 + ((lane >> 4) << 3)]);
            asm volatile("ldmatrix.sync.aligned.m8n8.x4.trans.shared.b16 {%0,%1,%2,%3}, [%4];"
                         : "=r"(b0), "=r"(b1), "=r"(b2), "=r"(b3) : "r"(baddr));
            asm volatile(
                "mma.sync.aligned.m16n8k16.row.col.f32.f16.f16.f32 "
                "{%0,%1,%2,%3}, {%4,%5,%6,%7}, {%8,%9}, {%0,%1,%2,%3};"
                : "+f"(acc[np * 2][0]), "+f"(acc[np * 2][1]),
                  "+f"(acc[np * 2][2]), "+f"(acc[np * 2][3])
                : "r"(a0), "r"(a1), "r"(a2), "r"(a3), "r"(b0), "r"(b1));
            asm volatile(
                "mma.sync.aligned.m16n8k16.row.col.f32.f16.f16.f32 "
                "{%0,%1,%2,%3}, {%4,%5,%6,%7}, {%8,%9}, {%0,%1,%2,%3};"
                : "+f"(acc[np * 2 + 1][0]), "+f"(acc[np * 2 + 1][1]),
                  "+f"(acc[np * 2 + 1][2]), "+f"(acc[np * 2 + 1][3])
                : "r"(a0), "r"(a1), "r"(a2), "r"(a3), "r"(b2), "r"(b3));
        }
    }
}

__device__ __forceinline__ void gemm_epilogue(float acc[8][4], __half* Y,
                                              int t, int mrow, int ncol0, int lane) {
    int r = lane >> 2, c = (lane & 3) * 2;
    int gr0 = t * 64 + mrow + r;
    int gr1 = gr0 + 8;
    float d0 = (gr0 < NN) ? g_dinv[gr0] : 0.f;
    float d1 = (gr1 < NN) ? g_dinv[gr1] : 0.f;
#pragma unroll
    for (int nt = 0; nt < 8; nt++) {
        int col = ncol0 + nt * 8 + c;
        if (gr0 < NN)
            *(__half2*)&Y[gr0 * FD + col] = __floats2half2_rn(acc[nt][0] * d0, acc[nt][1] * d0);
        if (gr1 < NN)
            *(__half2*)&Y[gr1 * FD + col] = __floats2half2_rn(acc[nt][2] * d1, acc[nt][3] * d1);
    }
}

// ---------------- persistent GEMM, fp16 input, tile range [t0, t1) ----------------
__global__ __launch_bounds__(256, 2) void gemm_pers16_kernel(const __half* __restrict__ X16,
                                                             const __half* __restrict__ W16,
                                                             __half* __restrict__ Y,
                                                             int t0, int t1) {
    extern __shared__ __half smemh[];
    __half* sW = smemh;
    __half* sA = smemh + 128 * LDSH;
    int tid = threadIdx.x;

    {
        const uint4* W4 = (const uint4*)W16;
        for (int i = tid; i < 128 * 16; i += 256) {
            int row = i >> 4, j = i & 15;
            *(uint4*)&sW[row * LDSH + j * 8] = W4[i];
        }
    }

    const uint4* Xq = (const uint4*)X16;  // 16 uint4 per row
    int warp = tid >> 5, lane = tid & 31;
    int mrow = (warp >> 1) * 16;
    int ncol0 = (warp & 1) * 64;

    uint4 xreg[4];
    {
        int t = t0 + blockIdx.x;
        if (t < t1) {
#pragma unroll
            for (int k = 0; k < 4; k++) {
                int i = tid + k * 256;
                int row = i >> 4, j = i & 15;
                int gr = t * 64 + row;
                xreg[k] = (gr < NN) ? Xq[gr * 16 + j] : make_uint4(0u, 0u, 0u, 0u);
            }
        }
    }

    for (int t = t0 + blockIdx.x; t < t1; t += gridDim.x) {
#pragma unroll
        for (int k = 0; k < 4; k++) {
            int i = tid + k * 256;
            int row = i >> 4, j = i & 15;
            *(uint4*)&sA[row * LDSH + j * 8] = xreg[k];
        }
        __syncthreads();

        int tn = t + gridDim.x;
        if (tn < t1) {
#pragma unroll
            for (int k = 0; k < 4; k++) {
                int i = tid + k * 256;
                int row = i >> 4, j = i & 15;
                int gr = tn * 64 + row;
                xreg[k] = (gr < NN) ? Xq[gr * 16 + j] : make_uint4(0u, 0u, 0u, 0u);
            }
        }

        float acc[8][4];
        gemm_tile_compute(sA, sW, mrow, ncol0, lane, acc);
        gemm_epilogue(acc, Y, t, mrow, ncol0, lane);
        __syncthreads();
    }
}

// ---------------- agg + bias + LN + ReLU: node range [nbeg, nbeg+ncnt) ----------------
__global__ __launch_bounds__(256) void agg_ln_relu_kernel(const __half* __restrict__ H,
                                                          __half* __restrict__ Z,
                                                          const float* __restrict__ bias,
                                                          const float* __restrict__ gam,
                                                          const float* __restrict__ bet,
                                                          int nbeg, int ncnt) {
    int gw = (blockIdx.x * blockDim.x + threadIdx.x) >> 5;
    if (gw >= ncnt) return;
    int lane = threadIdx.x & 31;
    int n = nbeg + gw;
    int r0 = g_rowptr[n], r1 = g_rowptr[n + 1];
    float dn = g_dinv[n];
    const uint2* Hu = (const uint2*)H;

    float f0 = 0.f, f1 = 0.f, f2 = 0.f, f3 = 0.f;

#define ADDU2(v)                                                  \
    {                                                             \
        float2 ta = __half22float2(*(__half2*)&(v).x);            \
        float2 tb = __half22float2(*(__half2*)&(v).y);            \
        f0 += ta.x; f1 += ta.y; f2 += tb.x; f3 += tb.y;           \
    }

    {
        uint2 sv = Hu[n * 32 + lane];
        ADDU2(sv)
    }

    int i = r0;
    for (; i + 8 <= r1; i += 8) {
        int s0 = g_esrc[i + 0];
        int s1 = g_esrc[i + 1];
        int s2 = g_esrc[i + 2];
        int s3 = g_esrc[i + 3];
        int s4 = g_esrc[i + 4];
        int s5 = g_esrc[i + 5];
        int s6 = g_esrc[i + 6];
        int s7 = g_esrc[i + 7];
        uint2 v0 = Hu[s0 * 32 + lane];
        uint2 v1 = Hu[s1 * 32 + lane];
        uint2 v2 = Hu[s2 * 32 + lane];
        uint2 v3 = Hu[s3 * 32 + lane];
        uint2 v4 = Hu[s4 * 32 + lane];
        uint2 v5 = Hu[s5 * 32 + lane];
        uint2 v6 = Hu[s6 * 32 + lane];
        uint2 v7 = Hu[s7 * 32 + lane];
        ADDU2(v0) ADDU2(v1) ADDU2(v2) ADDU2(v3)
        ADDU2(v4) ADDU2(v5) ADDU2(v6) ADDU2(v7)
    }
    for (; i < r1; i++) {
        int s = g_esrc[i];
        uint2 v = Hu[s * 32 + lane];
        ADDU2(v)
    }
#undef ADDU2

    const float4* b4p = (const float4*)bias;
    float4 b4 = b4p[lane];
    f0 = f0 * dn + b4.x;
    f1 = f1 * dn + b4.y;
    f2 = f2 * dn + b4.z;
    f3 = f3 * dn + b4.w;

    float s = f0 + f1 + f2 + f3;
#pragma unroll
    for (int o = 16; o; o >>= 1) s += __shfl_xor_sync(0xffffffffu, s, o);
    float mean = s * (1.0f / FD);
    f0 -= mean; f1 -= mean; f2 -= mean; f3 -= mean;
    float ss = f0 * f0 + f1 * f1 + f2 * f2 + f3 * f3;
#pragma unroll
    for (int o = 16; o; o >>= 1) ss += __shfl_xor_sync(0xffffffffu, ss, o);
    float rstd = rsqrtf(ss * (1.0f / FD) + 1e-5f);

    const float4* g4p = (const float4*)gam;
    const float4* e4p = (const float4*)bet;
    float4 g4 = g4p[lane], e4 = e4p[lane];
    float o0 = fmaxf(f0 * rstd * g4.x + e4.x, 0.f);
    float o1 = fmaxf(f1 * rstd * g4.y + e4.y, 0.f);
    float o2 = fmaxf(f2 * rstd * g4.z + e4.z, 0.f);
    float o3 = fmaxf(f3 * rstd * g4.w + e4.w, 0.f);
    __half2 p0 = __floats2half2_rn(o0, o1);
    __half2 p1 = __floats2half2_rn(o2, o3);
    uint2 st;
    st.x = *(unsigned*)&p0;
    st.y = *(unsigned*)&p1;
    ((uint2*)Z)[n * 32 + lane] = st;
}

// ---------------- fused gate MLP + exp + pooled accumulation, chunk range ----------------
__global__ __launch_bounds__(256) void gate_pool_kernel(const __half* __restrict__ Z,
                                                        const float* __restrict__ Wg1,
                                                        const float* __restrict__ bg1,
                                                        const float* __restrict__ Wg2,
                                                        const float* __restrict__ bg2,
                                                        const int* __restrict__ batch,
                                                        int cbeg, int cend) {
    __shared__ float sW1[FD * 64];
    __shared__ float sW2[64];
    __shared__ float sB1[64];
    int tid = threadIdx.x;
    for (int i = tid; i < FD * 64; i += 256) sW1[i] = Wg1[i];
    if (tid < 64) { sW2[tid] = Wg2[tid]; sB1[tid] = bg1[tid]; }
    __syncthreads();

    int warp = cbeg + blockIdx.x * 8 + (tid >> 5);
    if (warp >= cend) return;
    int lane = tid & 31;
    int j0 = lane * 2;
    const uint2* Z2 = (const uint2*)Z;
    float bg2v = bg2[0];
    float s2a = sW2[j0], s2b = sW2[j0 + 1];
    float b1a = sB1[j0], b1b = sB1[j0 + 1];

    int n0 = warp * 64;
    int nend = min(n0 + 64, NN);

    float4 pacc = make_float4(0.f, 0.f, 0.f, 0.f);
    float eacc = 0.f;
    int curb = -1;

    for (int base = n0; base < nend; base += 4) {
        float4 xv[4];
#pragma unroll
        for (int r = 0; r < 4; r++) {
            if (base + r < nend) {
                uint2 v = Z2[(base + r) * 32 + lane];
                float2 a = __half22float2(*(__half2*)&v.x);
                float2 b = __half22float2(*(__half2*)&v.y);
                xv[r] = make_float4(a.x, a.y, b.x, b.y);
            } else {
                xv[r] = make_float4(0.f, 0.f, 0.f, 0.f);
            }
        }
        unsigned long long acc[4];
#pragma unroll
        for (int r = 0; r < 4; r++) acc[r] = pk2(0.f, 0.f);

#pragma unroll
        for (int kl = 0; kl < 32; kl++) {
            float2 w0 = *(const float2*)&sW1[(kl * 4 + 0) * 64 + j0];
            float2 w1 = *(const float2*)&sW1[(kl * 4 + 1) * 64 + j0];
            float2 w2 = *(const float2*)&sW1[(kl * 4 + 2) * 64 + j0];
            float2 w3 = *(const float2*)&sW1[(kl * 4 + 3) * 64 + j0];
            unsigned long long p0 = pk2(w0.x, w0.y), p1 = pk2(w1.x, w1.y);
            unsigned long long p2 = pk2(w2.x, w2.y), p3 = pk2(w3.x, w3.y);
#pragma unroll
            for (int r = 0; r < 4; r++) {
                float b0 = __shfl_sync(0xffffffffu, xv[r].x, kl);
                float b1 = __shfl_sync(0xffffffffu, xv[r].y, kl);
                float b2 = __shfl_sync(0xffffffffu, xv[r].z, kl);
                float b3 = __shfl_sync(0xffffffffu, xv[r].w, kl);
                fma2(acc[r], p0, pk2(b0, b0));
                fma2(acc[r], p1, pk2(b1, b1));
                fma2(acc[r], p2, pk2(b2, b2));
                fma2(acc[r], p3, pk2(b3, b3));
            }
        }
#pragma unroll
        for (int r = 0; r < 4; r++) {
            int n = base + r;
            if (n >= nend) break;
            float h0, h1;
            upk2(acc[r], h0, h1);
            h0 = fmaxf(h0 + b1a, 0.f);
            h1 = fmaxf(h1 + b1b, 0.f);
            float part = h0 * s2a + h1 * s2b;
#pragma unroll
            for (int o = 16; o; o >>= 1) part += __shfl_xor_sync(0xffffffffu, part, o);
            float e = expf(part + bg2v);
            int b = batch[n];
            if (b != curb) {
                if (curb >= 0) {
                    float* p = &g_pooled[curb * FD + lane * 4];
                    atomicAdd(p + 0, pacc.x); atomicAdd(p + 1, pacc.y);
                    atomicAdd(p + 2, pacc.z); atomicAdd(p + 3, pacc.w);
                    if (lane == 0) atomicAdd(&g_denom[curb], eacc);
                    pacc = make_float4(0.f, 0.f, 0.f, 0.f);
                    eacc = 0.f;
                }
                curb = b;
            }
            pacc.x += e * xv[r].x; pacc.y += e * xv[r].y;
            pacc.z += e * xv[r].z; pacc.w += e * xv[r].w;
            eacc += e;
        }
    }
    if (curb >= 0) {
        float* p = &g_pooled[curb * FD + lane * 4];
        atomicAdd(p + 0, pacc.x); atomicAdd(p + 1, pacc.y);
        atomicAdd(p + 2, pacc.z); atomicAdd(p + 3, pacc.w);
        if (lane == 0) atomicAdd(&g_denom[curb], eacc);
    }
}

__global__ __launch_bounds__(256) void cls_kernel(const float* __restrict__ Wc,
                                                  const float* __restrict__ bc,
                                                  float* __restrict__ out) {
    int t = blockIdx.x * blockDim.x + threadIdx.x;
    if (t < NB * NC) {
        int b = t >> 4, c = t & 15;
        float s = 0.f;
        const float* p = &g_pooled[b * FD];
#pragma unroll 16
        for (int j = 0; j < FD; j++) s += p[j] * Wc[j * NC + c];
        out[t] = s / g_denom[b] + bc[c];
    }
}

// ---------------- launch ----------------
extern "C" void kernel_launch(void* const* d_in, const int* in_sizes, int n_in,
                              void* d_out, int out_size) {
    const float* x    = (const float*)d_in[0];
    const int*   ei   = (const int*)d_in[1];
    const int*   batch= (const int*)d_in[2];
    const float* W1   = (const float*)d_in[3];
    const float* b1   = (const float*)d_in[4];
    const float* g1   = (const float*)d_in[5];
    const float* be1  = (const float*)d_in[6];
    const float* W2   = (const float*)d_in[7];
    const float* b2   = (const float*)d_in[8];
    const float* g2   = (const float*)d_in[9];
    const float* be2  = (const float*)d_in[10];
    const float* Wg1  = (const float*)d_in[11];
    const float* bg1  = (const float*)d_in[12];
    const float* Wg2  = (const float*)d_in[13];
    const float* bg2  = (const float*)d_in[14];
    const float* Wc   = (const float*)d_in[15];
    const float* bc   = (const float*)d_in[16];
    float* out = (float*)d_out;

    const int* src = ei;
    const int* dst = ei + NE;

    const int GEMM_SMEM = (128 + 64) * LDSH * (int)sizeof(__half);  // 52224 B

    static cudaStream_t s1 = nullptr;
    static cudaEvent_t evFork = nullptr, evDinv = nullptr, evJoin = nullptr;
    static cudaEvent_t evA0 = nullptr, evA1 = nullptr, evG = nullptr;
    static cudaEvent_t evB0 = nullptr, evB1 = nullptr, evP = nullptr;
    static bool attr_done = false;
    if (!attr_done) {
        cudaFuncSetAttribute(gemm_pers16_kernel, cudaFuncAttributeMaxDynamicSharedMemorySize,
                             GEMM_SMEM);
        cudaStreamCreateWithFlags(&s1, cudaStreamNonBlocking);
        cudaEventCreateWithFlags(&evFork, cudaEventDisableTiming);
        cudaEventCreateWithFlags(&evDinv, cudaEventDisableTiming);
        cudaEventCreateWithFlags(&evJoin, cudaEventDisableTiming);
        cudaEventCreateWithFlags(&evA0, cudaEventDisableTiming);
        cudaEventCreateWithFlags(&evA1, cudaEventDisableTiming);
        cudaEventCreateWithFlags(&evG, cudaEventDisableTiming);
        cudaEventCreateWithFlags(&evB0, cudaEventDisableTiming);
        cudaEventCreateWithFlags(&evB1, cudaEventDisableTiming);
        cudaEventCreateWithFlags(&evP, cudaEventDisableTiming);
        attr_done = true;
    }

    __half* h16a; cudaGetSymbolAddress((void**)&h16a, g_h16a);
    __half* h16b; cudaGetSymbolAddress((void**)&h16b, g_h16b);
    __half* z16;  cudaGetSymbolAddress((void**)&z16, g_z16);
    __half* x16;  cudaGetSymbolAddress((void**)&x16, g_x16);
    __half* w16a; cudaGetSymbolAddress((void**)&w16a, g_W16a);
    __half* w16b; cudaGetSymbolAddress((void**)&w16b, g_W16b);

    const int GEMM_GRID = 296;
    const int NH0 = NSPLIT;             // 49984 nodes first half
    const int NH1 = NN - NSPLIT;        // 50016 nodes second half

    // fork: W + X conversions (independent of everything) on s1
    cudaEventRecord(evFork, 0);
    cudaStreamWaitEvent(s1, evFork, 0);
    w16_kernel<<<32, 256, 0, s1>>>(W1, w16a);
    w16_kernel<<<32, 256, 0, s1>>>(W2, w16b);
    x16_kernel<<<(NN * FD / 4 + 255) / 256, 256, 0, s1>>>(x, x16);

    // dinv production chain on main stream
    init_kernel<<<(NN + 255) / 256, 256>>>();
    deg_kernel<<<(NE / 4 + 255) / 256, 256>>>(dst);
    scanA_kernel<<<NPB, 512>>>();
    cudaEventRecord(evDinv, 0);

    // s1: GEMM-1 (fp16 input) writes h16a; overlaps rest of CSR build
    cudaStreamWaitEvent(s1, evDinv, 0);
    gemm_pers16_kernel<<<GEMM_GRID, 256, GEMM_SMEM, s1>>>(x16, w16a, h16a, 0, NT_TOTAL);
    cudaEventRecord(evJoin, s1);

    scanC_kernel<<<NPB, 512>>>();
    fill_kernel<<<(NE + 255) / 256, 256>>>(src, dst);

    // ---- layer 1 agg (reads h16a, writes z16) pipelined with layer-2 gemm (reads z16 rows, writes h16b) ----
    cudaStreamWaitEvent(0, evJoin, 0);
    agg_ln_relu_kernel<<<(NH0 * 32 + 255) / 256, 256>>>(h16a, z16, b1, g1, be1, 0, NH0);
    cudaEventRecord(evA0, 0);
    cudaStreamWaitEvent(s1, evA0, 0);
    gemm_pers16_kernel<<<GEMM_GRID, 256, GEMM_SMEM, s1>>>(z16, w16b, h16b, 0, NT_H0);

    agg_ln_relu_kernel<<<(NH1 * 32 + 255) / 256, 256>>>(h16a, z16, b1, g1, be1, NH0, NH1);
    cudaEventRecord(evA1, 0);
    cudaStreamWaitEvent(s1, evA1, 0);
    gemm_pers16_kernel<<<GEMM_GRID, 256, GEMM_SMEM, s1>>>(z16, w16b, h16b, NT_H0, NT_TOTAL);
    cudaEventRecord(evG, s1);

    // ---- layer 2 agg (reads h16b globally -> needs full gemm2; writes z16) pipelined with gate_pool (reads z16 rows) ----
    cudaStreamWaitEvent(0, evG, 0);
    agg_ln_relu_kernel<<<(NH0 * 32 + 255) / 256, 256>>>(h16b, z16, b2, g2, be2, 0, NH0);
    cudaEventRecord(evB0, 0);
    cudaStreamWaitEvent(s1, evB0, 0);
    gate_pool_kernel<<<(NT_H0 + 7) / 8, 256, 0, s1>>>(z16, Wg1, bg1, Wg2, bg2, batch,
                                                      0, NT_H0);

    agg_ln_relu_kernel<<<(NH1 * 32 + 255) / 256, 256>>>(h16b, z16, b2, g2, be2, NH0, NH1);
    cudaEventRecord(evB1, 0);
    cudaStreamWaitEvent(s1, evB1, 0);
    gate_pool_kernel<<<(NT_TOTAL - NT_H0 + 7) / 8, 256, 0, s1>>>(z16, Wg1, bg1, Wg2, bg2,
                                                                 batch, NT_H0, NT_TOTAL);
    cudaEventRecord(evP, s1);

    // classifier
    cudaStreamWaitEvent(0, evP, 0);
    cls_kernel<<<(NB * NC + 255) / 256, 256>>>(Wc, bc, out);
}

// round 17
// speedup vs baseline: 1.0943x; 1.0943x over previous
#include <cuda_runtime.h>
#include <cuda_fp16.h>
#include <math.h>

#define NN 100000
#define NE 1600000
#define NB 64
#define FD 128
#define NC 16
#define NPB 196  // ceil(NN/512) scan blocks
#define LDSH 136 // padded smem leading dim (halves) for conflict-free ldmatrix
#define NCHUNK ((NN + 63) / 64)  // 1563 pooling chunks

// ---------------- scratch (device globals; no allocations) ----------------
__device__ __half   g_h16[NN * FD];   // fp16 scaled intermediate h~ = dinv * (X@W)
__device__ __half   g_z16[NN * FD];   // fp16 Z = relu(LN(agg))
__device__ __half   g_W16a[FD * FD];  // W1 in fp16
__device__ __half   g_W16b[FD * FD];  // W2 in fp16
__device__ float    g_dinv[NN];
__device__ int      g_indeg[NN];
__device__ int      g_ctr[NN];
__device__ int      g_rowptr[NN + 1];
__device__ int      g_part[NPB];
__device__ int      g_esrc[NE];
__device__ float    g_denom[NB];
__device__ float    g_pooled[NB * FD];   // unnormalized: sum of exp(gate)*z

// ---------------- helpers ----------------
__device__ __forceinline__ unsigned long long pk2(float lo, float hi) {
    unsigned long long r;
    asm("mov.b64 %0, {%1,%2};" : "=l"(r) : "f"(lo), "f"(hi));
    return r;
}
__device__ __forceinline__ void upk2(unsigned long long v, float& lo, float& hi) {
    asm("mov.b64 {%0,%1}, %2;" : "=f"(lo), "=f"(hi) : "l"(v));
}
__device__ __forceinline__ void fma2(unsigned long long& acc, unsigned long long a,
                                     unsigned long long b) {
    asm("fma.rn.f32x2 %0, %1, %2, %0;" : "+l"(acc) : "l"(a), "l"(b));
}

// ---------------- setup kernels ----------------
__global__ __launch_bounds__(256) void init_kernel() {
    int i = blockIdx.x * blockDim.x + threadIdx.x;
    if (i < NN) { g_indeg[i] = 0; g_ctr[i] = 0; }
    if (i < NB * FD) g_pooled[i] = 0.f;
    if (i < NB) g_denom[i] = 0.f;
    if (i == 0) g_rowptr[NN] = NE;
}

__global__ __launch_bounds__(256) void w16_kernel(const float* __restrict__ W,
                                                  __half* __restrict__ O) {
    int i = blockIdx.x * 256 + threadIdx.x;
    if (i < FD * FD / 2) {
        float2 v = ((const float2*)W)[i];
        ((__half2*)O)[i] = __floats2half2_rn(v.x, v.y);
    }
}

__global__ __launch_bounds__(256) void deg_kernel(const int* __restrict__ dst) {
    int idx = blockIdx.x * blockDim.x + threadIdx.x;
    if (idx < NE / 4) {
        int4 d = ((const int4*)dst)[idx];
        atomicAdd(&g_indeg[d.x], 1);
        atomicAdd(&g_indeg[d.y], 1);
        atomicAdd(&g_indeg[d.z], 1);
        atomicAdd(&g_indeg[d.w], 1);
    }
}

__global__ __launch_bounds__(512) void scanA_kernel() {
    int t = threadIdx.x, b = blockIdx.x;
    int idx = b * 512 + t;
    int v = (idx < NN) ? g_indeg[idx] : 0;
    if (idx < NN) g_dinv[idx] = rsqrtf((float)(v + 1));
    int x = v;
#pragma unroll
    for (int o = 16; o; o >>= 1) x += __shfl_xor_sync(0xffffffffu, x, o);
    __shared__ int wsum[16];
    int lane = t & 31, wid = t >> 5;
    if (lane == 0) wsum[wid] = x;
    __syncthreads();
    if (t == 0) {
        int s = 0;
#pragma unroll
        for (int w = 0; w < 16; w++) s += wsum[w];
        g_part[b] = s;
    }
}

// fused: per-block scan of indeg + redundant scan of g_part
__global__ __launch_bounds__(512) void scanC_kernel() {
    int t = threadIdx.x, b = blockIdx.x;
    int lane = t & 31, wid = t >> 5;

    __shared__ int sp[256];
    __shared__ int blockoff;
    {
        int v = (t < NPB) ? g_part[t] : 0;
        if (t < 256) {
            int x = v;
#pragma unroll
            for (int o = 1; o < 32; o <<= 1) {
                int y = __shfl_up_sync(0xffffffffu, x, o);
                if (lane >= o) x += y;
            }
            sp[t] = x;
        }
        __syncthreads();
        if (t < 256 && wid > 0) {
            int add = 0;
#pragma unroll
            for (int w = 0; w < 8; w++)
                if (w < wid) add += sp[w * 32 + 31];
            sp[t] += add;
        }
        __syncthreads();
        if (t == 0) blockoff = (b > 0) ? sp[b - 1] : 0;
        __syncthreads();
    }

    int idx = b * 512 + t;
    int v = (idx < NN) ? g_indeg[idx] : 0;
    int x = v;
#pragma unroll
    for (int o = 1; o < 32; o <<= 1) {
        int y = __shfl_up_sync(0xffffffffu, x, o);
        if (lane >= o) x += y;
    }
    __shared__ int wsum[16];
    if (lane == 31) wsum[wid] = x;
    __syncthreads();
    if (wid == 0) {
        int s = (lane < 16) ? wsum[lane] : 0;
#pragma unroll
        for (int o = 1; o < 16; o <<= 1) {
            int y = __shfl_up_sync(0xffffffffu, s, o);
            if (lane >= o) s += y;
        }
        if (lane < 16) wsum[lane] = s;
    }
    __syncthreads();
    int excl = x - v + (wid > 0 ? wsum[wid - 1] : 0);
    if (idx < NN) g_rowptr[idx] = blockoff + excl;
}

__global__ __launch_bounds__(256) void fill_kernel(const int* __restrict__ src,
                                                   const int* __restrict__ dst) {
    int e = blockIdx.x * blockDim.x + threadIdx.x;
    if (e < NE) {
        int d = dst[e];
        int p = g_rowptr[d] + atomicAdd(&g_ctr[d], 1);
        g_esrc[p] = src[e];
    }
}

// ---------------- shared GEMM core (sA/sW staged fp16) ----------------
__device__ __forceinline__ void gemm_tile_compute(const __half* sA, const __half* sW,
                                                  int mrow, int ncol0, int lane,
                                                  float acc[8][4]) {
#pragma unroll
    for (int nt = 0; nt < 8; nt++)
        acc[nt][0] = acc[nt][1] = acc[nt][2] = acc[nt][3] = 0.f;
#pragma unroll
    for (int k0 = 0; k0 < 128; k0 += 16) {
        unsigned a0, a1, a2, a3;
        {
            int arow = mrow + (lane & 15);
            int acol = k0 + ((lane >> 4) << 3);
            unsigned aaddr = (unsigned)__cvta_generic_to_shared(&sA[arow * LDSH + acol]);
            asm volatile("ldmatrix.sync.aligned.m8n8.x4.shared.b16 {%0,%1,%2,%3}, [%4];"
                         : "=r"(a0), "=r"(a1), "=r"(a2), "=r"(a3) : "r"(aaddr));
        }
#pragma unroll
        for (int np = 0; np < 4; np++) {
            unsigned b0, b1, b2, b3;
            unsigned baddr = (unsigned)__cvta_generic_to_shared(
                &sW[(k0 + (lane & 15)) * LDSH + ncol0 + np * 16 + ((lane >> 4) << 3)]);
            asm volatile("ldmatrix.sync.aligned.m8n8.x4.trans.shared.b16 {%0,%1,%2,%3}, [%4];"
                         : "=r"(b0), "=r"(b1), "=r"(b2), "=r"(b3) : "r"(baddr));
            asm volatile(
                "mma.sync.aligned.m16n8k16.row.col.f32.f16.f16.f32 "
                "{%0,%1,%2,%3}, {%4,%5,%6,%7}, {%8,%9}, {%0,%1,%2,%3};"
                : "+f"(acc[np * 2][0]), "+f"(acc[np * 2][1]),
                  "+f"(acc[np * 2][2]), "+f"(acc[np * 2][3])
                : "r"(a0), "r"(a1), "r"(a2), "r"(a3), "r"(b0), "r"(b1));
            asm volatile(
                "mma.sync.aligned.m16n8k16.row.col.f32.f16.f16.f32 "
                "{%0,%1,%2,%3}, {%4,%5,%6,%7}, {%8,%9}, {%0,%1,%2,%3};"
                : "+f"(acc[np * 2 + 1][0]), "+f"(acc[np * 2 + 1][1]),
                  "+f"(acc[np * 2 + 1][2]), "+f"(acc[np * 2 + 1][3])
                : "r"(a0), "r"(a1), "r"(a2), "r"(a3), "r"(b2), "r"(b3));
        }
    }
}

__device__ __forceinline__ void gemm_epilogue(float acc[8][4], __half* Y,
                                              int t, int mrow, int ncol0, int lane) {
    int r = lane >> 2, c = (lane & 3) * 2;
    int gr0 = t * 64 + mrow + r;
    int gr1 = gr0 + 8;
    float d0 = (gr0 < NN) ? g_dinv[gr0] : 0.f;
    float d1 = (gr1 < NN) ? g_dinv[gr1] : 0.f;
#pragma unroll
    for (int nt = 0; nt < 8; nt++) {
        int col = ncol0 + nt * 8 + c;
        if (gr0 < NN)
            *(__half2*)&Y[gr0 * FD + col] = __floats2half2_rn(acc[nt][0] * d0, acc[nt][1] * d0);
        if (gr1 < NN)
            *(__half2*)&Y[gr1 * FD + col] = __floats2half2_rn(acc[nt][2] * d1, acc[nt][3] * d1);
    }
}

// ---------------- persistent GEMM, fp32 input: H~ = dinv * (X @ W16) ----------------
__global__ __launch_bounds__(256, 2) void gemm_pers_kernel(const float* __restrict__ X,
                                                           const __half* __restrict__ W16,
                                                           __half* __restrict__ Y) {
    extern __shared__ __half smemh[];
    __half* sW = smemh;               // [128][LDSH]
    __half* sA = smemh + 128 * LDSH;  // [64][LDSH]
    int tid = threadIdx.x;

    {
        const uint4* W4 = (const uint4*)W16;
        for (int i = tid; i < 128 * 16; i += 256) {
            int row = i >> 4, j = i & 15;
            *(uint4*)&sW[row * LDSH + j * 8] = W4[i];
        }
    }

    const int nt_total = (NN + 63) >> 6;
    const float4* X4 = (const float4*)X;
    int warp = tid >> 5, lane = tid & 31;
    int mrow = (warp >> 1) * 16;
    int ncol0 = (warp & 1) * 64;

    float4 xreg[8];
    {
        int t = blockIdx.x;
#pragma unroll
        for (int k = 0; k < 8; k++) {
            int i = tid + k * 256;
            int row = i >> 5, j = i & 31;
            int gr = t * 64 + row;
            xreg[k] = (gr < NN) ? X4[gr * 32 + j] : make_float4(0.f, 0.f, 0.f, 0.f);
        }
    }

    for (int t = blockIdx.x; t < nt_total; t += gridDim.x) {
#pragma unroll
        for (int k = 0; k < 8; k++) {
            int i = tid + k * 256;
            int row = i >> 5, j = i & 31;
            *(__half2*)&sA[row * LDSH + j * 4]     = __floats2half2_rn(xreg[k].x, xreg[k].y);
            *(__half2*)&sA[row * LDSH + j * 4 + 2] = __floats2half2_rn(xreg[k].z, xreg[k].w);
        }
        __syncthreads();

        int tn = t + gridDim.x;
        if (tn < nt_total) {
#pragma unroll
            for (int k = 0; k < 8; k++) {
                int i = tid + k * 256;
                int row = i >> 5, j = i & 31;
                int gr = tn * 64 + row;
                xreg[k] = (gr < NN) ? X4[gr * 32 + j] : make_float4(0.f, 0.f, 0.f, 0.f);
            }
        }

        float acc[8][4];
        gemm_tile_compute(sA, sW, mrow, ncol0, lane, acc);
        gemm_epilogue(acc, Y, t, mrow, ncol0, lane);
        __syncthreads();
    }
}

// ---------------- persistent GEMM, fp16 input: H~ = dinv * (Z16 @ W16) ----------------
__global__ __launch_bounds__(256, 2) void gemm_pers16_kernel(const __half* __restrict__ X16,
                                                             const __half* __restrict__ W16,
                                                             __half* __restrict__ Y) {
    extern __shared__ __half smemh[];
    __half* sW = smemh;
    __half* sA = smemh + 128 * LDSH;
    int tid = threadIdx.x;

    {
        const uint4* W4 = (const uint4*)W16;
        for (int i = tid; i < 128 * 16; i += 256) {
            int row = i >> 4, j = i & 15;
            *(uint4*)&sW[row * LDSH + j * 8] = W4[i];
        }
    }

    const int nt_total = (NN + 63) >> 6;
    const uint4* Xq = (const uint4*)X16;  // 16 uint4 per row
    int warp = tid >> 5, lane = tid & 31;
    int mrow = (warp >> 1) * 16;
    int ncol0 = (warp & 1) * 64;

    uint4 xreg[4];
    {
        int t = blockIdx.x;
#pragma unroll
        for (int k = 0; k < 4; k++) {
            int i = tid + k * 256;
            int row = i >> 4, j = i & 15;
            int gr = t * 64 + row;
            xreg[k] = (gr < NN) ? Xq[gr * 16 + j] : make_uint4(0u, 0u, 0u, 0u);
        }
    }

    for (int t = blockIdx.x; t < nt_total; t += gridDim.x) {
#pragma unroll
        for (int k = 0; k < 4; k++) {
            int i = tid + k * 256;
            int row = i >> 4, j = i & 15;
            *(uint4*)&sA[row * LDSH + j * 8] = xreg[k];
        }
        __syncthreads();

        int tn = t + gridDim.x;
        if (tn < nt_total) {
#pragma unroll
            for (int k = 0; k < 4; k++) {
                int i = tid + k * 256;
                int row = i >> 4, j = i & 15;
                int gr = tn * 64 + row;
                xreg[k] = (gr < NN) ? Xq[gr * 16 + j] : make_uint4(0u, 0u, 0u, 0u);
            }
        }

        float acc[8][4];
        gemm_tile_compute(sA, sW, mrow, ncol0, lane, acc);
        gemm_epilogue(acc, Y, t, mrow, ncol0, lane);
        __syncthreads();
    }
}

// ---------------- agg + bias + LN + ReLU: full-warp rows, uint2/lane, 8-deep MLP ----------------
__global__ __launch_bounds__(256) void agg_ln_relu_kernel(const __half* __restrict__ H,
                                                          __half* __restrict__ Z,
                                                          const float* __restrict__ bias,
                                                          const float* __restrict__ gam,
                                                          const float* __restrict__ bet) {
    int gw = (blockIdx.x * blockDim.x + threadIdx.x) >> 5;
    if (gw >= NN) return;
    int lane = threadIdx.x & 31;
    int n = gw;
    int r0 = g_rowptr[n], r1 = g_rowptr[n + 1];
    float dn = g_dinv[n];
    const uint2* Hu = (const uint2*)H;  // 32 uint2 per row

    float f0 = 0.f, f1 = 0.f, f2 = 0.f, f3 = 0.f;

#define ADDU2(v)                                                  \
    {                                                             \
        float2 ta = __half22float2(*(__half2*)&(v).x);            \
        float2 tb = __half22float2(*(__half2*)&(v).y);            \
        f0 += ta.x; f1 += ta.y; f2 += tb.x; f3 += tb.y;           \
    }

    {
        uint2 sv = Hu[n * 32 + lane];
        ADDU2(sv)
    }

    int i = r0;
    for (; i + 8 <= r1; i += 8) {
        int s0 = g_esrc[i + 0];
        int s1 = g_esrc[i + 1];
        int s2 = g_esrc[i + 2];
        int s3 = g_esrc[i + 3];
        int s4 = g_esrc[i + 4];
        int s5 = g_esrc[i + 5];
        int s6 = g_esrc[i + 6];
        int s7 = g_esrc[i + 7];
        uint2 v0 = Hu[s0 * 32 + lane];
        uint2 v1 = Hu[s1 * 32 + lane];
        uint2 v2 = Hu[s2 * 32 + lane];
        uint2 v3 = Hu[s3 * 32 + lane];
        uint2 v4 = Hu[s4 * 32 + lane];
        uint2 v5 = Hu[s5 * 32 + lane];
        uint2 v6 = Hu[s6 * 32 + lane];
        uint2 v7 = Hu[s7 * 32 + lane];
        ADDU2(v0) ADDU2(v1) ADDU2(v2) ADDU2(v3)
        ADDU2(v4) ADDU2(v5) ADDU2(v6) ADDU2(v7)
    }
    for (; i < r1; i++) {
        int s = g_esrc[i];
        uint2 v = Hu[s * 32 + lane];
        ADDU2(v)
    }
#undef ADDU2

    const float4* b4p = (const float4*)bias;
    float4 b4 = b4p[lane];
    f0 = f0 * dn + b4.x;
    f1 = f1 * dn + b4.y;
    f2 = f2 * dn + b4.z;
    f3 = f3 * dn + b4.w;

    float s = f0 + f1 + f2 + f3;
#pragma unroll
    for (int o = 16; o; o >>= 1) s += __shfl_xor_sync(0xffffffffu, s, o);
    float mean = s * (1.0f / FD);
    f0 -= mean; f1 -= mean; f2 -= mean; f3 -= mean;
    float ss = f0 * f0 + f1 * f1 + f2 * f2 + f3 * f3;
#pragma unroll
    for (int o = 16; o; o >>= 1) ss += __shfl_xor_sync(0xffffffffu, ss, o);
    float rstd = rsqrtf(ss * (1.0f / FD) + 1e-5f);

    const float4* g4p = (const float4*)gam;
    const float4* e4p = (const float4*)bet;
    float4 g4 = g4p[lane], e4 = e4p[lane];
    float o0 = fmaxf(f0 * rstd * g4.x + e4.x, 0.f);
    float o1 = fmaxf(f1 * rstd * g4.y + e4.y, 0.f);
    float o2 = fmaxf(f2 * rstd * g4.z + e4.z, 0.f);
    float o3 = fmaxf(f3 * rstd * g4.w + e4.w, 0.f);
    __half2 p0 = __floats2half2_rn(o0, o1);
    __half2 p1 = __floats2half2_rn(o2, o3);
    uint2 st;
    st.x = *(unsigned*)&p0;
    st.y = *(unsigned*)&p1;
    ((uint2*)Z)[n * 32 + lane] = st;
}

// ---------------- fused gate MLP + exp + pooled accumulation (fp16 Z) ----------------
__global__ __launch_bounds__(256) void gate_pool_kernel(const __half* __restrict__ Z,
                                                        const float* __restrict__ Wg1,
                                                        const float* __restrict__ bg1,
                                                        const float* __restrict__ Wg2,
                                                        const float* __restrict__ bg2,
                                                        const int* __restrict__ batch) {
    __shared__ float sW1[FD * 64];
    __shared__ float sW2[64];
    __shared__ float sB1[64];
    int tid = threadIdx.x;
    for (int i = tid; i < FD * 64; i += 256) sW1[i] = Wg1[i];
    if (tid < 64) { sW2[tid] = Wg2[tid]; sB1[tid] = bg1[tid]; }
    __syncthreads();

    int warp = blockIdx.x * 8 + (tid >> 5);
    if (warp >= NCHUNK) return;
    int lane = tid & 31;
    int j0 = lane * 2;
    const uint2* Z2 = (const uint2*)Z;
    float bg2v = bg2[0];
    float s2a = sW2[j0], s2b = sW2[j0 + 1];
    float b1a = sB1[j0], b1b = sB1[j0 + 1];

    int n0 = warp * 64;
    int nend = min(n0 + 64, NN);

    float4 pacc = make_float4(0.f, 0.f, 0.f, 0.f);
    float eacc = 0.f;
    int curb = -1;

    for (int base = n0; base < nend; base += 4) {
        float4 xv[4];
#pragma unroll
        for (int r = 0; r < 4; r++) {
            if (base + r < nend) {
                uint2 v = Z2[(base + r) * 32 + lane];
                float2 a = __half22float2(*(__half2*)&v.x);
                float2 b = __half22float2(*(__half2*)&v.y);
                xv[r] = make_float4(a.x, a.y, b.x, b.y);
            } else {
                xv[r] = make_float4(0.f, 0.f, 0.f, 0.f);
            }
        }
        unsigned long long acc[4];
#pragma unroll
        for (int r = 0; r < 4; r++) acc[r] = pk2(0.f, 0.f);

#pragma unroll
        for (int kl = 0; kl < 32; kl++) {
            float2 w0 = *(const float2*)&sW1[(kl * 4 + 0) * 64 + j0];
            float2 w1 = *(const float2*)&sW1[(kl * 4 + 1) * 64 + j0];
            float2 w2 = *(const float2*)&sW1[(kl * 4 + 2) * 64 + j0];
            float2 w3 = *(const float2*)&sW1[(kl * 4 + 3) * 64 + j0];
            unsigned long long p0 = pk2(w0.x, w0.y), p1 = pk2(w1.x, w1.y);
            unsigned long long p2 = pk2(w2.x, w2.y), p3 = pk2(w3.x, w3.y);
#pragma unroll
            for (int r = 0; r < 4; r++) {
                float b0 = __shfl_sync(0xffffffffu, xv[r].x, kl);
                float b1 = __shfl_sync(0xffffffffu, xv[r].y, kl);
                float b2 = __shfl_sync(0xffffffffu, xv[r].z, kl);
                float b3 = __shfl_sync(0xffffffffu, xv[r].w, kl);
                fma2(acc[r], p0, pk2(b0, b0));
                fma2(acc[r], p1, pk2(b1, b1));
                fma2(acc[r], p2, pk2(b2, b2));
                fma2(acc[r], p3, pk2(b3, b3));
            }
        }
#pragma unroll
        for (int r = 0; r < 4; r++) {
            int n = base + r;
            if (n >= nend) break;
            float h0, h1;
            upk2(acc[r], h0, h1);
            h0 = fmaxf(h0 + b1a, 0.f);
            h1 = fmaxf(h1 + b1b, 0.f);
            float part = h0 * s2a + h1 * s2b;
#pragma unroll
            for (int o = 16; o; o >>= 1) part += __shfl_xor_sync(0xffffffffu, part, o);
            float e = expf(part + bg2v);
            int b = batch[n];
            if (b != curb) {
                if (curb >= 0) {
                    float* p = &g_pooled[curb * FD + lane * 4];
                    atomicAdd(p + 0, pacc.x); atomicAdd(p + 1, pacc.y);
                    atomicAdd(p + 2, pacc.z); atomicAdd(p + 3, pacc.w);
                    if (lane == 0) atomicAdd(&g_denom[curb], eacc);
                    pacc = make_float4(0.f, 0.f, 0.f, 0.f);
                    eacc = 0.f;
                }
                curb = b;
            }
            pacc.x += e * xv[r].x; pacc.y += e * xv[r].y;
            pacc.z += e * xv[r].z; pacc.w += e * xv[r].w;
            eacc += e;
        }
    }
    if (curb >= 0) {
        float* p = &g_pooled[curb * FD + lane * 4];
        atomicAdd(p + 0, pacc.x); atomicAdd(p + 1, pacc.y);
        atomicAdd(p + 2, pacc.z); atomicAdd(p + 3, pacc.w);
        if (lane == 0) atomicAdd(&g_denom[curb], eacc);
    }
}

__global__ __launch_bounds__(256) void cls_kernel(const float* __restrict__ Wc,
                                                  const float* __restrict__ bc,
                                                  float* __restrict__ out) {
    int t = blockIdx.x * blockDim.x + threadIdx.x;
    if (t < NB * NC) {
        int b = t >> 4, c = t & 15;
        float s = 0.f;
        const float* p = &g_pooled[b * FD];
#pragma unroll 16
        for (int j = 0; j < FD; j++) s += p[j] * Wc[j * NC + c];
        out[t] = s / g_denom[b] + bc[c];
    }
}

// ---------------- launch ----------------
extern "C" void kernel_launch(void* const* d_in, const int* in_sizes, int n_in,
                              void* d_out, int out_size) {
    const float* x    = (const float*)d_in[0];
    const int*   ei   = (const int*)d_in[1];
    const int*   batch= (const int*)d_in[2];
    const float* W1   = (const float*)d_in[3];
    const float* b1   = (const float*)d_in[4];
    const float* g1   = (const float*)d_in[5];
    const float* be1  = (const float*)d_in[6];
    const float* W2   = (const float*)d_in[7];
    const float* b2   = (const float*)d_in[8];
    const float* g2   = (const float*)d_in[9];
    const float* be2  = (const float*)d_in[10];
    const float* Wg1  = (const float*)d_in[11];
    const float* bg1  = (const float*)d_in[12];
    const float* Wg2  = (const float*)d_in[13];
    const float* bg2  = (const float*)d_in[14];
    const float* Wc   = (const float*)d_in[15];
    const float* bc   = (const float*)d_in[16];
    float* out = (float*)d_out;

    const int* src = ei;
    const int* dst = ei + NE;

    const int GEMM_SMEM = (128 + 64) * LDSH * (int)sizeof(__half);  // 52224 B

    static cudaStream_t s1 = nullptr;
    static cudaEvent_t evFork = nullptr, evDinv = nullptr, evJoin = nullptr;
    static bool attr_done = false;
    if (!attr_done) {
        cudaFuncSetAttribute(gemm_pers_kernel, cudaFuncAttributeMaxDynamicSharedMemorySize,
                             GEMM_SMEM);
        cudaFuncSetAttribute(gemm_pers16_kernel, cudaFuncAttributeMaxDynamicSharedMemorySize,
                             GEMM_SMEM);
        cudaStreamCreateWithFlags(&s1, cudaStreamNonBlocking);
        cudaEventCreateWithFlags(&evFork, cudaEventDisableTiming);
        cudaEventCreateWithFlags(&evDinv, cudaEventDisableTiming);
        cudaEventCreateWithFlags(&evJoin, cudaEventDisableTiming);
        attr_done = true;
    }

    __half* h16;  cudaGetSymbolAddress((void**)&h16, g_h16);
    __half* z16;  cudaGetSymbolAddress((void**)&z16, g_z16);
    __half* w16a; cudaGetSymbolAddress((void**)&w16a, g_W16a);
    __half* w16b; cudaGetSymbolAddress((void**)&w16b, g_W16b);

    const int GEMM_GRID = 296;

    // fork immediately: W conversions are independent of everything
    cudaEventRecord(evFork, 0);
    cudaStreamWaitEvent(s1, evFork, 0);
    w16_kernel<<<32, 256, 0, s1>>>(W1, w16a);
    w16_kernel<<<32, 256, 0, s1>>>(W2, w16b);

    // dinv production chain on main stream
    init_kernel<<<(NN + 255) / 256, 256>>>();
    deg_kernel<<<(NE / 4 + 255) / 256, 256>>>(dst);
    scanA_kernel<<<NPB, 512>>>();
    cudaEventRecord(evDinv, 0);

    // s1: GEMM-1 (needs x, W16a, dinv) overlaps rest of CSR build
    cudaStreamWaitEvent(s1, evDinv, 0);
    gemm_pers_kernel<<<GEMM_GRID, 256, GEMM_SMEM, s1>>>(x, w16a, h16);
    cudaEventRecord(evJoin, s1);

    scanC_kernel<<<NPB, 512>>>();
    fill_kernel<<<(NE + 255) / 256, 256>>>(src, dst);

    // join: agg1 needs both CSR and GEMM-1 output
    cudaStreamWaitEvent(0, evJoin, 0);
    agg_ln_relu_kernel<<<(NN * 32 + 255) / 256, 256>>>(h16, z16, b1, g1, be1);
    // layer 2 (fp16 input)
    gemm_pers16_kernel<<<GEMM_GRID, 256, GEMM_SMEM>>>(z16, w16b, h16);
    agg_ln_relu_kernel<<<(NN * 32 + 255) / 256, 256>>>(h16, z16, b2, g2, be2);

    // fused attention pooling (fp16 Z)
    gate_pool_kernel<<<(NCHUNK + 7) / 8, 256>>>(z16, Wg1, bg1, Wg2, bg2, batch);

    // classifier (divides by denom)
    cls_kernel<<<(NB * NC + 255) / 256, 256>>>(Wc, bc, out);
}